// round 11
// baseline (speedup 1.0000x reference)
#include <cuda_runtime.h>
#include <cstdint>
#include <math.h>

#define Sx 512
#define Bx 64
#define Hx 256
#define Lx 6
#define G3 768          // 3*H
#define DHx 512         // 2*H
#define M_TOT (Sx*Bx)   // 32768

typedef unsigned long long ull;

// ---------------- device scratch (static: no allocation allowed) ----------------
__device__ float g_gxT[2][(size_t)Sx*G3*Bx];          // [dir][s][gate*256+j][b] (bias added)
__device__ float g_io[(size_t)Sx*Bx*DHx];             // layer input/output (S,B,2H)
__device__ __align__(16) float g_hI[2][2][Hx*Bx];     // [dir][pp][k2*128 + b*2 + (k&1)]
__device__ unsigned g_flags[2][64][32];               // per-dir per-block step flag (128B lines)

__device__ __forceinline__ unsigned f2tf32(float f){
    unsigned u;
    asm("cvt.rna.tf32.f32 %0,%1;" : "=r"(u) : "f"(f));
    return u;
}

// =================================================================================
// gate_x GEMM, tf32 tensor cores (proven R8): block 128x128, BK=16, 8 warps,
// warp tile 64x32. Writes transposed gxT with bias added.
// =================================================================================
template<int K>
__global__ void __launch_bounds__(256,2) gatex_gemm(
    const float* __restrict__ xin,
    const float* __restrict__ Wbase,   // [2][768][K]
    const float* __restrict__ bias)    // [2][768]
{
    __shared__ unsigned As[16][136];
    __shared__ unsigned Bs[16][136];

    const int dir = blockIdx.z;
    const float* A = (K == 128) ? xin : g_io;
    const float* W = Wbase + (size_t)dir * G3 * K;
    const int n0 = blockIdx.x * 128;
    const int m0 = blockIdx.y * 128;
    const int tid = threadIdx.x;
    const int row  = tid >> 1;
    const int part = tid & 1;
    const int lane = tid & 31;
    const int w    = tid >> 5;
    const int wm = (w & 1) * 64;
    const int wn = (w >> 1) * 32;
    const int g = lane >> 2;
    const int t = lane & 3;

    float acc[4][4][4];
    #pragma unroll
    for (int mt = 0; mt < 4; mt++)
        #pragma unroll
        for (int nt = 0; nt < 4; nt++)
            #pragma unroll
            for (int i = 0; i < 4; i++) acc[mt][nt][i] = 0.f;

    const float* Ald = A + (size_t)(m0 + row) * K + part * 4;
    const float* Wld = W + (size_t)(n0 + row) * K + part * 4;

    float4 av0 = *(const float4*)(Ald);
    float4 av1 = *(const float4*)(Ald + 8);
    float4 wv0 = *(const float4*)(Wld);
    float4 wv1 = *(const float4*)(Wld + 8);

    for (int kt = 0; kt < K; kt += 16){
        const int k0 = part * 4;
        As[k0+0][row] = f2tf32(av0.x); As[k0+1][row] = f2tf32(av0.y);
        As[k0+2][row] = f2tf32(av0.z); As[k0+3][row] = f2tf32(av0.w);
        As[k0+8][row] = f2tf32(av1.x); As[k0+9][row] = f2tf32(av1.y);
        As[k0+10][row] = f2tf32(av1.z); As[k0+11][row] = f2tf32(av1.w);
        Bs[k0+0][row] = f2tf32(wv0.x); Bs[k0+1][row] = f2tf32(wv0.y);
        Bs[k0+2][row] = f2tf32(wv0.z); Bs[k0+3][row] = f2tf32(wv0.w);
        Bs[k0+8][row] = f2tf32(wv1.x); Bs[k0+9][row] = f2tf32(wv1.y);
        Bs[k0+10][row] = f2tf32(wv1.z); Bs[k0+11][row] = f2tf32(wv1.w);
        __syncthreads();
        if (kt + 16 < K){
            av0 = *(const float4*)(Ald + kt + 16);
            av1 = *(const float4*)(Ald + kt + 24);
            wv0 = *(const float4*)(Wld + kt + 16);
            wv1 = *(const float4*)(Wld + kt + 24);
        }
        #pragma unroll
        for (int c = 0; c < 2; c++){
            unsigned af[4][4], bf[4][2];
            #pragma unroll
            for (int mt = 0; mt < 4; mt++){
                const int m = wm + mt*16 + g;
                af[mt][0] = As[c*8 + t][m];
                af[mt][1] = As[c*8 + t][m + 8];
                af[mt][2] = As[c*8 + t + 4][m];
                af[mt][3] = As[c*8 + t + 4][m + 8];
            }
            #pragma unroll
            for (int nt = 0; nt < 4; nt++){
                const int n = wn + nt*8 + g;
                bf[nt][0] = Bs[c*8 + t][n];
                bf[nt][1] = Bs[c*8 + t + 4][n];
            }
            #pragma unroll
            for (int mt = 0; mt < 4; mt++)
                #pragma unroll
                for (int nt = 0; nt < 4; nt++)
                    asm volatile(
                        "mma.sync.aligned.m16n8k8.row.col.f32.tf32.tf32.f32 "
                        "{%0,%1,%2,%3},{%4,%5,%6,%7},{%8,%9},{%0,%1,%2,%3};"
                        : "+f"(acc[mt][nt][0]), "+f"(acc[mt][nt][1]),
                          "+f"(acc[mt][nt][2]), "+f"(acc[mt][nt][3])
                        : "r"(af[mt][0]), "r"(af[mt][1]), "r"(af[mt][2]), "r"(af[mt][3]),
                          "r"(bf[nt][0]), "r"(bf[nt][1]));
        }
        __syncthreads();
    }

    float* out = g_gxT[dir];
    const float* bs = bias + dir * G3;
    #pragma unroll
    for (int mt = 0; mt < 4; mt++){
        #pragma unroll
        for (int nt = 0; nt < 4; nt++){
            const int mr = m0 + wm + mt*16 + g;
            const int nc = n0 + wn + nt*8 + 2*t;
            const float b0 = bs[nc], b1 = bs[nc + 1];
            {
                const int s = mr >> 6, b = mr & 63;
                out[((size_t)s*G3 + nc    )*Bx + b] = acc[mt][nt][0] + b0;
                out[((size_t)s*G3 + nc + 1)*Bx + b] = acc[mt][nt][1] + b1;
            }
            {
                const int m2 = mr + 8;
                const int s = m2 >> 6, b = m2 & 63;
                out[((size_t)s*G3 + nc    )*Bx + b] = acc[mt][nt][2] + b0;
                out[((size_t)s*G3 + nc + 1)*Bx + b] = acc[mt][nt][3] + b1;
            }
        }
    }
}

// =================================================================================
// Persistent GRU layer (R10 structure; barrier replaced by distributed flags):
// 128 blocks (64/dir), 512 threads = 16 warps. Warp ks owns k2-slice [8ks,8ks+8),
// ALL 4 j columns. Two-phase smem reduction; distributed epilogue on tid<256.
// Sync: each block st.release's its OWN flag (separate 128B line — zero atomic
// serialization); lanes 0-15 of every block poll all 64 flags directly.
// =================================================================================
__global__ void __launch_bounds__(512,1) gru_layer(
    const float* __restrict__ h0_l,    // [2][B][H]
    const float* __restrict__ whh_l,   // [2][768][256]
    const float* __restrict__ bhh_l,   // [2][768]
    float* __restrict__ hn_out)        // [2][B][H] slice of d_out
{
    __shared__ __align__(16) float ws[4][128][8];    // [jj][k2]: wr0,wr1,wz0,wz1,wn0,wn1,pad
    __shared__ float red[8][4][3][64];               // [ks&7][jj][gate][b]

    const int bx   = blockIdx.x;
    const int dir  = bx >> 6;
    const int jblk = bx & 63;
    const int j0   = jblk * 4;
    const int tid  = threadIdx.x;
    const int bo   = tid & 31;
    const int ks   = tid >> 5;          // warp id = k-slice (0..15)
    const int jE   = tid >> 6;          // epilogue local j (valid for tid<256)
    const int bE   = tid & 63;          // epilogue batch
    const int jG   = j0 + jE;           // epilogue global j

    // stage packed weights: k = 2*k2 + e
    for (int i = tid; i < 1024; i += 512){
        const int jj = i >> 8, k = i & 255, k2 = k >> 1, e = k & 1;
        const size_t base = ((size_t)dir * G3 + j0 + jj) * Hx + k;
        ws[jj][k2][e]     = whh_l[base];
        ws[jj][k2][2 + e] = whh_l[base + (size_t)Hx*Hx];
        ws[jj][k2][4 + e] = whh_l[base + (size_t)2*Hx*Hx];
    }

    // stage h0 into interleaved layout (this block's 4 j columns)
    if (tid < 256){
        const int js = j0 + jE;
        g_hI[dir][0][(js >> 1)*128 + 2*bE + (js & 1)] =
            h0_l[(size_t)dir*Bx*Hx + (size_t)bE*Hx + js];
    }

    const float br = bhh_l[dir*G3 + (jG & 255)];
    const float bz = bhh_l[dir*G3 + Hx + (jG & 255)];
    const float bn = bhh_l[dir*G3 + 2*Hx + (jG & 255)];

    unsigned* myflag = &g_flags[dir][jblk][0];
    unsigned* fbase  = &g_flags[dir][0][0];
    unsigned bstep = 1;

    // -------- flag barrier: publish own, poll all 64 --------
    #define FLAG_BAR()                                                              \
    do {                                                                            \
        __syncthreads();                                                            \
        if (tid == 0)                                                               \
            asm volatile("st.global.release.gpu.u32 [%0],%1;"                       \
                         :: "l"(myflag), "r"(bstep) : "memory");                    \
        if (tid < 16){                                                              \
            unsigned ok;                                                            \
            do {                                                                    \
                ok = 1u;                                                            \
                _Pragma("unroll")                                                   \
                for (int i = 0; i < 4; i++){                                        \
                    unsigned v;                                                     \
                    asm volatile("ld.global.acquire.gpu.u32 %0,[%1];"               \
                                 : "=r"(v) : "l"(fbase + (tid*4 + i)*32) : "memory");\
                    ok &= (unsigned)((int)(v - bstep) >= 0);                        \
                }                                                                   \
            } while (__ballot_sync(0xFFFFu, ok) != 0xFFFFu);                        \
        }                                                                           \
        bstep++;                                                                    \
        __syncthreads();                                                            \
    } while (0)

    FLAG_BAR();

    unsigned wsa[4];
    #pragma unroll
    for (int jj = 0; jj < 4; jj++)
        wsa[jj] = (unsigned)__cvta_generic_to_shared(&ws[jj][ks*8][0]);

    const float* gxb = g_gxT[dir];
    const int hEoff = ((jG & 255) >> 1)*128 + 2*bE + (jG & 1);

    int cur = 0;
    for (int t = 0; t < Sx; t++){
        const int ta = dir ? (Sx - 1 - t) : t;

        // issue critical-path h loads FIRST: 4-deep pipeline over 8 iters
        const float* hp = g_hI[dir][cur] + ks*8*128 + 4*bo;
        ull hc[4][2];
        #pragma unroll
        for (int p = 0; p < 4; p++)
            asm volatile("ld.global.cg.v2.b64 {%0,%1},[%2];"
                         : "=l"(hc[p][0]), "=l"(hc[p][1]) : "l"(hp + p*128));

        // epilogue prefetch (tid<256 only; consumed after reduction)
        float xr = 0.f, xz = 0.f, xn = 0.f, hprev = 0.f;
        if (tid < 256){
            const float* p = gxb + (size_t)ta*G3*Bx + bE;
            xr = __ldg(p + (size_t)(0*Hx + jG)*Bx);
            xz = __ldg(p + (size_t)(1*Hx + jG)*Bx);
            xn = __ldg(p + (size_t)(2*Hx + jG)*Bx);
            asm volatile("ld.global.cg.f32 %0,[%1];"
                         : "=f"(hprev) : "l"(g_hI[dir][cur] + hEoff));
        }

        ull acc[24];
        #pragma unroll
        for (int i = 0; i < 24; i++) acc[i] = 0ull;

        #pragma unroll
        for (int k2 = 0; k2 < 8; k2++){
            const ull h01 = hc[k2 & 3][0];
            const ull h23 = hc[k2 & 3][1];
            #pragma unroll
            for (int jj = 0; jj < 4; jj++){
                ull wr, wz, wn;
                asm volatile("ld.shared.v2.u64 {%0,%1},[%2];"
                             : "=l"(wr), "=l"(wz) : "r"(wsa[jj] + k2*32));
                asm volatile("ld.shared.u64 %0,[%1];"
                             : "=l"(wn) : "r"(wsa[jj] + k2*32 + 16));
                asm("fma.rn.f32x2 %0,%1,%2,%0;" : "+l"(acc[jj*6+0]) : "l"(h01), "l"(wr));
                asm("fma.rn.f32x2 %0,%1,%2,%0;" : "+l"(acc[jj*6+1]) : "l"(h23), "l"(wr));
                asm("fma.rn.f32x2 %0,%1,%2,%0;" : "+l"(acc[jj*6+2]) : "l"(h01), "l"(wz));
                asm("fma.rn.f32x2 %0,%1,%2,%0;" : "+l"(acc[jj*6+3]) : "l"(h23), "l"(wz));
                asm("fma.rn.f32x2 %0,%1,%2,%0;" : "+l"(acc[jj*6+4]) : "l"(h01), "l"(wn));
                asm("fma.rn.f32x2 %0,%1,%2,%0;" : "+l"(acc[jj*6+5]) : "l"(h23), "l"(wn));
            }
            if (k2 < 4)
                asm volatile("ld.global.cg.v2.b64 {%0,%1},[%2];"
                             : "=l"(hc[k2 & 3][0]), "=l"(hc[k2 & 3][1])
                             : "l"(hp + (k2 + 4)*128));
        }

        // collapse k-parity pairs
        float v[4][3][2];
        #pragma unroll
        for (int jj = 0; jj < 4; jj++)
            #pragma unroll
            for (int g = 0; g < 3; g++){
                float l0, h0f, l1, h1f;
                asm("mov.b64 {%0,%1},%2;" : "=f"(l0), "=f"(h0f) : "l"(acc[jj*6 + 2*g]));
                asm("mov.b64 {%0,%1},%2;" : "=f"(l1), "=f"(h1f) : "l"(acc[jj*6 + 2*g + 1]));
                v[jj][g][0] = l0 + h0f;
                v[jj][g][1] = l1 + h1f;
            }

        // two-phase reduction: warps 0-7 write, warps 8-15 add
        if (ks < 8){
            #pragma unroll
            for (int jj = 0; jj < 4; jj++)
                #pragma unroll
                for (int g = 0; g < 3; g++)
                    *(float2*)&red[ks][jj][g][2*bo] = make_float2(v[jj][g][0], v[jj][g][1]);
        }
        __syncthreads();
        if (ks >= 8){
            #pragma unroll
            for (int jj = 0; jj < 4; jj++)
                #pragma unroll
                for (int g = 0; g < 3; g++){
                    float2 q = *(float2*)&red[ks - 8][jj][g][2*bo];
                    q.x += v[jj][g][0]; q.y += v[jj][g][1];
                    *(float2*)&red[ks - 8][jj][g][2*bo] = q;
                }
        }
        __syncthreads();

        // distributed epilogue: thread = (jE, bE), tid<256
        if (tid < 256){
            float sr = 0.f, sz = 0.f, sn = 0.f;
            #pragma unroll
            for (int q = 0; q < 8; q++){
                sr += red[q][jE][0][bE];
                sz += red[q][jE][1][bE];
                sn += red[q][jE][2][bE];
            }
            const float r = __fdividef(1.f, 1.f + __expf(-(xr + sr + br)));
            const float z = __fdividef(1.f, 1.f + __expf(-(xz + sz + bz)));
            const float targ = xn + r * (sn + bn);
            const float nn = 1.f - __fdividef(2.f, __expf(2.f*targ) + 1.f);
            const float hnew = (1.f - z) * nn + z * hprev;

            g_hI[dir][cur ^ 1][hEoff] = hnew;
            g_io[((size_t)ta*Bx + bE)*DHx + dir*Hx + jG] = hnew;
            if (t == Sx - 1)
                hn_out[(size_t)dir*Bx*Hx + (size_t)bE*Hx + jG] = hnew;
        }

        if (t < Sx - 1){
            FLAG_BAR();
        }
        cur ^= 1;
    }
    #undef FLAG_BAR
}

// =================================================================================
extern "C" void kernel_launch(void* const* d_in, const int* in_sizes, int n_in,
                              void* d_out, int out_size)
{
    const float* x     = (const float*)d_in[0];   // (512,64,128)
    const float* h0    = (const float*)d_in[1];   // (12,64,256)
    const float* w_ih0 = (const float*)d_in[2];   // (2,768,128)
    const float* w_ih  = (const float*)d_in[3];   // (5,2,768,512)
    const float* w_hh  = (const float*)d_in[4];   // (6,2,768,256)
    const float* b_ih  = (const float*)d_in[5];   // (6,2,768)
    const float* b_hh  = (const float*)d_in[6];   // (6,2,768)
    float* out = (float*)d_out;                   // (12,64,256)

    void* flagp = nullptr;
    cudaGetSymbolAddress(&flagp, g_flags);

    for (int layer = 0; layer < Lx; layer++){
        dim3 gg(G3/128, M_TOT/128, 2);
        if (layer == 0){
            gatex_gemm<128><<<gg, 256>>>(x, w_ih0, b_ih);
        } else {
            gatex_gemm<512><<<gg, 256>>>(
                x,
                w_ih + (size_t)(layer-1) * 2 * G3 * 512,
                b_ih + (size_t)layer * 2 * G3);
        }
        cudaMemsetAsync(flagp, 0, sizeof(unsigned) * 2 * 64 * 32);
        gru_layer<<<128, 512>>>(
            h0   + (size_t)layer * 2 * Bx * Hx,
            w_hh + (size_t)layer * 2 * G3 * Hx,
            b_hh + (size_t)layer * 2 * G3,
            out  + (size_t)layer * 2 * Bx * Hx);
    }
}

// round 12
// speedup vs baseline: 1.3091x; 1.3091x over previous
#include <cuda_runtime.h>
#include <cstdint>
#include <math.h>

#define Sx 512
#define Bx 64
#define Hx 256
#define Lx 6
#define G3 768          // 3*H
#define DHx 512         // 2*H
#define M_TOT (Sx*Bx)   // 32768

typedef unsigned long long ull;

// ---------------- device scratch (static: no allocation allowed) ----------------
__device__ float g_gxT[2][(size_t)Sx*G3*Bx];   // [dir][s][gate*256+j][b] (bias added)
__device__ float g_io[(size_t)Sx*Bx*DHx];      // layer input/output (S,B,2H)

__device__ __forceinline__ unsigned f2tf32(float f){
    unsigned u;
    asm("cvt.rna.tf32.f32 %0,%1;" : "=r"(u) : "f"(f));
    return u;
}
__device__ __forceinline__ unsigned ctarank(){
    unsigned r; asm("mov.u32 %0, %%cluster_ctarank;" : "=r"(r)); return r;
}

// =================================================================================
// gate_x GEMM, tf32 tensor cores (proven R8): block 128x128, BK=16, 8 warps,
// warp tile 64x32. Writes transposed gxT with bias added.
// =================================================================================
template<int K>
__global__ void __launch_bounds__(256,2) gatex_gemm(
    const float* __restrict__ xin,
    const float* __restrict__ Wbase,   // [2][768][K]
    const float* __restrict__ bias)    // [2][768]
{
    __shared__ unsigned As[16][136];
    __shared__ unsigned Bs[16][136];

    const int dir = blockIdx.z;
    const float* A = (K == 128) ? xin : g_io;
    const float* W = Wbase + (size_t)dir * G3 * K;
    const int n0 = blockIdx.x * 128;
    const int m0 = blockIdx.y * 128;
    const int tid = threadIdx.x;
    const int row  = tid >> 1;
    const int part = tid & 1;
    const int lane = tid & 31;
    const int w    = tid >> 5;
    const int wm = (w & 1) * 64;
    const int wn = (w >> 1) * 32;
    const int g = lane >> 2;
    const int t = lane & 3;

    float acc[4][4][4];
    #pragma unroll
    for (int mt = 0; mt < 4; mt++)
        #pragma unroll
        for (int nt = 0; nt < 4; nt++)
            #pragma unroll
            for (int i = 0; i < 4; i++) acc[mt][nt][i] = 0.f;

    const float* Ald = A + (size_t)(m0 + row) * K + part * 4;
    const float* Wld = W + (size_t)(n0 + row) * K + part * 4;

    float4 av0 = *(const float4*)(Ald);
    float4 av1 = *(const float4*)(Ald + 8);
    float4 wv0 = *(const float4*)(Wld);
    float4 wv1 = *(const float4*)(Wld + 8);

    for (int kt = 0; kt < K; kt += 16){
        const int k0 = part * 4;
        As[k0+0][row] = f2tf32(av0.x); As[k0+1][row] = f2tf32(av0.y);
        As[k0+2][row] = f2tf32(av0.z); As[k0+3][row] = f2tf32(av0.w);
        As[k0+8][row] = f2tf32(av1.x); As[k0+9][row] = f2tf32(av1.y);
        As[k0+10][row] = f2tf32(av1.z); As[k0+11][row] = f2tf32(av1.w);
        Bs[k0+0][row] = f2tf32(wv0.x); Bs[k0+1][row] = f2tf32(wv0.y);
        Bs[k0+2][row] = f2tf32(wv0.z); Bs[k0+3][row] = f2tf32(wv0.w);
        Bs[k0+8][row] = f2tf32(wv1.x); Bs[k0+9][row] = f2tf32(wv1.y);
        Bs[k0+10][row] = f2tf32(wv1.z); Bs[k0+11][row] = f2tf32(wv1.w);
        __syncthreads();
        if (kt + 16 < K){
            av0 = *(const float4*)(Ald + kt + 16);
            av1 = *(const float4*)(Ald + kt + 24);
            wv0 = *(const float4*)(Wld + kt + 16);
            wv1 = *(const float4*)(Wld + kt + 24);
        }
        #pragma unroll
        for (int c = 0; c < 2; c++){
            unsigned af[4][4], bf[4][2];
            #pragma unroll
            for (int mt = 0; mt < 4; mt++){
                const int m = wm + mt*16 + g;
                af[mt][0] = As[c*8 + t][m];
                af[mt][1] = As[c*8 + t][m + 8];
                af[mt][2] = As[c*8 + t + 4][m];
                af[mt][3] = As[c*8 + t + 4][m + 8];
            }
            #pragma unroll
            for (int nt = 0; nt < 4; nt++){
                const int n = wn + nt*8 + g;
                bf[nt][0] = Bs[c*8 + t][n];
                bf[nt][1] = Bs[c*8 + t + 4][n];
            }
            #pragma unroll
            for (int mt = 0; mt < 4; mt++)
                #pragma unroll
                for (int nt = 0; nt < 4; nt++)
                    asm volatile(
                        "mma.sync.aligned.m16n8k8.row.col.f32.tf32.tf32.f32 "
                        "{%0,%1,%2,%3},{%4,%5,%6,%7},{%8,%9},{%0,%1,%2,%3};"
                        : "+f"(acc[mt][nt][0]), "+f"(acc[mt][nt][1]),
                          "+f"(acc[mt][nt][2]), "+f"(acc[mt][nt][3])
                        : "r"(af[mt][0]), "r"(af[mt][1]), "r"(af[mt][2]), "r"(af[mt][3]),
                          "r"(bf[nt][0]), "r"(bf[nt][1]));
        }
        __syncthreads();
    }

    float* out = g_gxT[dir];
    const float* bs = bias + dir * G3;
    #pragma unroll
    for (int mt = 0; mt < 4; mt++){
        #pragma unroll
        for (int nt = 0; nt < 4; nt++){
            const int mr = m0 + wm + mt*16 + g;
            const int nc = n0 + wn + nt*8 + 2*t;
            const float b0 = bs[nc], b1 = bs[nc + 1];
            {
                const int s = mr >> 6, b = mr & 63;
                out[((size_t)s*G3 + nc    )*Bx + b] = acc[mt][nt][0] + b0;
                out[((size_t)s*G3 + nc + 1)*Bx + b] = acc[mt][nt][1] + b1;
            }
            {
                const int m2 = mr + 8;
                const int s = m2 >> 6, b = m2 & 63;
                out[((size_t)s*G3 + nc    )*Bx + b] = acc[mt][nt][2] + b0;
                out[((size_t)s*G3 + nc + 1)*Bx + b] = acc[mt][nt][3] + b1;
            }
        }
    }
}

// =================================================================================
// Cluster GRU layer: grid 128 = 32 clusters x 4 CTAs, 384 threads/CTA.
// Cluster = (dir, 4 batches) — fully independent sequential chain, NO global sync.
// CTA q owns j-quarter [64q,64q+64): W slice (3x64x256) interleaved [2j][2k] in
// SMEM (conflict-free LDS.128). Thread = (ks 0..3, gate, jl2): 2 j x 4 b x 64 k,
// f32x2 over k-parity, h broadcast from SMEM. ks-partials reduced via SMEM;
// epilogue (tid<256) writes hnew into all 4 CTAs' next-h via st.shared::cluster;
// one cluster.sync per step.
// =================================================================================
#define WS_BYTES (96*129*16)                 // 198,144
#define HS_BYTES 4096
#define RED_OFF  (WS_BYTES + 2*HS_BYTES)     // 206,336
#define SMEM_GRU (RED_OFF + 12288)           // 218,624

__global__ void __launch_bounds__(384,1) __cluster_dims__(4,1,1)
gru_layer(
    const float* __restrict__ h0_l,    // [2][B][H]
    const float* __restrict__ whh_l,   // [2][768][256]
    const float* __restrict__ bhh_l,   // [2][768]
    float* __restrict__ hn_out)        // [2][B][H] slice of d_out
{
    extern __shared__ __align__(16) float smem[];
    const unsigned sb = (unsigned)__cvta_generic_to_shared(smem);

    const int cid  = blockIdx.x >> 2;   // cluster id 0..31
    const int q    = (int)ctarank();    // j-quarter 0..3
    const int dir  = cid >> 4;
    const int bgrp = cid & 15;
    const int tid  = threadIdx.x;

    // compute-phase mapping
    const int ks   = tid / 96;          // 0..3 (k-quarter)
    const int rem  = tid - ks*96;
    const int gate = rem >> 5;          // 0..2
    const int jl2  = rem & 31;          // j-pair index

    // epilogue mapping (tid<256)
    const int jl = tid >> 2;            // 0..63
    const int b  = tid & 3;
    const int jglob = q*64 + jl;
    const int bglob = bgrp*4 + b;

    // ---- stage W interleaved: ws[(gate*32+jl2)*129 + k2][4] = {j0e0,j0e1,j1e0,j1e1}
    for (int i = tid; i < 49152; i += 384){
        const int f = i & 3, jsel = f >> 1, e = f & 1;
        const int k2 = (i >> 2) & 127;
        const int rw = i >> 9;                 // 0..95
        const int gg = rw >> 5, jj2 = rw & 31;
        const int jloc = 2*jj2 + jsel;
        smem[((gg*32 + jj2)*129 + k2)*4 + f] =
            whh_l[((size_t)dir*G3 + gg*Hx + q*64 + jloc)*Hx + 2*k2 + e];
    }

    // ---- stage h0 into hsA: [k2][b][e], full 256 j, own 4 batches
    float* hsA = smem + WS_BYTES/4;
    for (int i = tid; i < 1024; i += 384){
        const int j = i >> 2, bb = i & 3;
        hsA[(j >> 1)*8 + bb*2 + (j & 1)] =
            h0_l[(size_t)dir*Bx*Hx + (size_t)(bgrp*4 + bb)*Hx + j];
    }

    // epilogue biases
    float br = 0.f, bz = 0.f, bn = 0.f;
    if (tid < 256){
        br = bhh_l[dir*G3 + jglob];
        bz = bhh_l[dir*G3 + Hx + jglob];
        bn = bhh_l[dir*G3 + 2*Hx + jglob];
    }
    __syncthreads();

    const unsigned wadr = sb + (unsigned)(((gate*32 + jl2)*129 + ks*32)*16);
    float* redp = smem + RED_OFF/4;
    const float* gxb = g_gxT[dir];
    const int hEidx = (jglob >> 1)*8 + b*2 + (jglob & 1);

    int cur = 0;
    for (int t = 0; t < Sx; t++){
        const int ta = dir ? (Sx - 1 - t) : t;
        const unsigned hsC_u = sb + WS_BYTES + (unsigned)cur*HS_BYTES;
        const unsigned hsN_u = sb + WS_BYTES + (unsigned)(cur ^ 1)*HS_BYTES;

        // ---- compute: 32 k2-iters, 2 j x 4 b x 3-gate-split
        ull aJ0B0=0, aJ0B1=0, aJ0B2=0, aJ0B3=0, aJ1B0=0, aJ1B1=0, aJ1B2=0, aJ1B3=0;
        const unsigned hbase = hsC_u + (unsigned)(ks*32*32);
        #pragma unroll 8
        for (int k = 0; k < 32; k++){
            ull wj0, wj1, hb0, hb1, hb2, hb3;
            asm volatile("ld.shared.v2.u64 {%0,%1},[%2];"
                         : "=l"(wj0), "=l"(wj1) : "r"(wadr + k*16));
            asm volatile("ld.shared.v2.u64 {%0,%1},[%2];"
                         : "=l"(hb0), "=l"(hb1) : "r"(hbase + k*32));
            asm volatile("ld.shared.v2.u64 {%0,%1},[%2];"
                         : "=l"(hb2), "=l"(hb3) : "r"(hbase + k*32 + 16));
            asm("fma.rn.f32x2 %0,%1,%2,%0;" : "+l"(aJ0B0) : "l"(wj0), "l"(hb0));
            asm("fma.rn.f32x2 %0,%1,%2,%0;" : "+l"(aJ0B1) : "l"(wj0), "l"(hb1));
            asm("fma.rn.f32x2 %0,%1,%2,%0;" : "+l"(aJ0B2) : "l"(wj0), "l"(hb2));
            asm("fma.rn.f32x2 %0,%1,%2,%0;" : "+l"(aJ0B3) : "l"(wj0), "l"(hb3));
            asm("fma.rn.f32x2 %0,%1,%2,%0;" : "+l"(aJ1B0) : "l"(wj1), "l"(hb0));
            asm("fma.rn.f32x2 %0,%1,%2,%0;" : "+l"(aJ1B1) : "l"(wj1), "l"(hb1));
            asm("fma.rn.f32x2 %0,%1,%2,%0;" : "+l"(aJ1B2) : "l"(wj1), "l"(hb2));
            asm("fma.rn.f32x2 %0,%1,%2,%0;" : "+l"(aJ1B3) : "l"(wj1), "l"(hb3));
        }
        // collapse k-parity, publish partials: red[(ks*3+gate)*64 + j][b]
        {
            float4 v0, v1; float lo, hi;
            asm("mov.b64 {%0,%1},%2;" : "=f"(lo), "=f"(hi) : "l"(aJ0B0)); v0.x = lo + hi;
            asm("mov.b64 {%0,%1},%2;" : "=f"(lo), "=f"(hi) : "l"(aJ0B1)); v0.y = lo + hi;
            asm("mov.b64 {%0,%1},%2;" : "=f"(lo), "=f"(hi) : "l"(aJ0B2)); v0.z = lo + hi;
            asm("mov.b64 {%0,%1},%2;" : "=f"(lo), "=f"(hi) : "l"(aJ0B3)); v0.w = lo + hi;
            asm("mov.b64 {%0,%1},%2;" : "=f"(lo), "=f"(hi) : "l"(aJ1B0)); v1.x = lo + hi;
            asm("mov.b64 {%0,%1},%2;" : "=f"(lo), "=f"(hi) : "l"(aJ1B1)); v1.y = lo + hi;
            asm("mov.b64 {%0,%1},%2;" : "=f"(lo), "=f"(hi) : "l"(aJ1B2)); v1.z = lo + hi;
            asm("mov.b64 {%0,%1},%2;" : "=f"(lo), "=f"(hi) : "l"(aJ1B3)); v1.w = lo + hi;
            float4* rp = (float4*)(redp + ((ks*3 + gate)*64 + 2*jl2)*4);
            rp[0] = v0;
            rp[1] = v1;
        }
        __syncthreads();

        // ---- epilogue: thread = (jl, b), tid<256
        if (tid < 256){
            float sr = 0.f, sz = 0.f, sn = 0.f;
            #pragma unroll
            for (int kq = 0; kq < 4; kq++){
                sr += redp[((kq*3 + 0)*64 + jl)*4 + b];
                sz += redp[((kq*3 + 1)*64 + jl)*4 + b];
                sn += redp[((kq*3 + 2)*64 + jl)*4 + b];
            }
            const float* p = gxb + (size_t)ta*G3*Bx + bglob;
            const float xr = __ldg(p + (size_t)(0*Hx + jglob)*Bx);
            const float xz = __ldg(p + (size_t)(1*Hx + jglob)*Bx);
            const float xn = __ldg(p + (size_t)(2*Hx + jglob)*Bx);
            float hprev;
            asm volatile("ld.shared.f32 %0,[%1];"
                         : "=f"(hprev) : "r"(hsC_u + (unsigned)(hEidx*4)));

            const float r = __fdividef(1.f, 1.f + __expf(-(xr + sr + br)));
            const float z = __fdividef(1.f, 1.f + __expf(-(xz + sz + bz)));
            const float targ = xn + r * (sn + bn);
            const float nn = 1.f - __fdividef(2.f, __expf(2.f*targ) + 1.f);
            const float hnew = (1.f - z) * nn + z * hprev;

            if (t < Sx - 1){
                const unsigned off = hsN_u + (unsigned)(hEidx*4);
                #pragma unroll
                for (int rk = 0; rk < 4; rk++){
                    asm volatile(
                        "{ .reg .b32 ra;\n\t"
                        "mapa.shared::cluster.u32 ra, %0, %1;\n\t"
                        "st.shared::cluster.f32 [ra], %2; }"
                        :: "r"(off), "r"(rk), "f"(hnew) : "memory");
                }
            }
            g_io[((size_t)ta*Bx + bglob)*DHx + dir*Hx + jglob] = hnew;
            if (t == Sx - 1)
                hn_out[(size_t)dir*Bx*Hx + (size_t)bglob*Hx + jglob] = hnew;
        }

        if (t < Sx - 1){
            asm volatile("barrier.cluster.arrive.aligned;" ::: "memory");
            asm volatile("barrier.cluster.wait.aligned;" ::: "memory");
        }
        cur ^= 1;
    }
}

// =================================================================================
extern "C" void kernel_launch(void* const* d_in, const int* in_sizes, int n_in,
                              void* d_out, int out_size)
{
    const float* x     = (const float*)d_in[0];   // (512,64,128)
    const float* h0    = (const float*)d_in[1];   // (12,64,256)
    const float* w_ih0 = (const float*)d_in[2];   // (2,768,128)
    const float* w_ih  = (const float*)d_in[3];   // (5,2,768,512)
    const float* w_hh  = (const float*)d_in[4];   // (6,2,768,256)
    const float* b_ih  = (const float*)d_in[5];   // (6,2,768)
    const float* b_hh  = (const float*)d_in[6];   // (6,2,768)
    float* out = (float*)d_out;                   // (12,64,256)

    cudaFuncSetAttribute(gru_layer, cudaFuncAttributeMaxDynamicSharedMemorySize, SMEM_GRU);

    for (int layer = 0; layer < Lx; layer++){
        dim3 gg(G3/128, M_TOT/128, 2);
        if (layer == 0){
            gatex_gemm<128><<<gg, 256>>>(x, w_ih0, b_ih);
        } else {
            gatex_gemm<512><<<gg, 256>>>(
                x,
                w_ih + (size_t)(layer-1) * 2 * G3 * 512,
                b_ih + (size_t)layer * 2 * G3);
        }
        gru_layer<<<128, 384, SMEM_GRU>>>(
            h0   + (size_t)layer * 2 * Bx * Hx,
            w_hh + (size_t)layer * 2 * G3 * Hx,
            b_hh + (size_t)layer * 2 * G3,
            out  + (size_t)layer * 2 * Bx * Hx);
    }
}

// round 13
// speedup vs baseline: 1.4980x; 1.1443x over previous
#include <cuda_runtime.h>
#include <cstdint>
#include <math.h>

#define Sx 512
#define Bx 64
#define Hx 256
#define Lx 6
#define G3 768          // 3*H
#define DHx 512         // 2*H
#define M_TOT (Sx*Bx)   // 32768

typedef unsigned long long ull;

// ---------------- device scratch (static: no allocation allowed) ----------------
__device__ float g_gxT[2][(size_t)Sx*G3*Bx];   // [dir][s][gate*256+j][b] (bias added)
__device__ float g_io[(size_t)Sx*Bx*DHx];      // layer input/output (S,B,2H)

__device__ __forceinline__ unsigned f2tf32(float f){
    unsigned u;
    asm("cvt.rna.tf32.f32 %0,%1;" : "=r"(u) : "f"(f));
    return u;
}
__device__ __forceinline__ unsigned ctarank(){
    unsigned r; asm("mov.u32 %0, %%cluster_ctarank;" : "=r"(r)); return r;
}

// =================================================================================
// gate_x GEMM, tf32 tensor cores (proven R8): block 128x128, BK=16, 8 warps,
// warp tile 64x32. Writes transposed gxT with bias added.
// =================================================================================
template<int K>
__global__ void __launch_bounds__(256,2) gatex_gemm(
    const float* __restrict__ xin,
    const float* __restrict__ Wbase,   // [2][768][K]
    const float* __restrict__ bias)    // [2][768]
{
    __shared__ unsigned As[16][136];
    __shared__ unsigned Bs[16][136];

    const int dir = blockIdx.z;
    const float* A = (K == 128) ? xin : g_io;
    const float* W = Wbase + (size_t)dir * G3 * K;
    const int n0 = blockIdx.x * 128;
    const int m0 = blockIdx.y * 128;
    const int tid = threadIdx.x;
    const int row  = tid >> 1;
    const int part = tid & 1;
    const int lane = tid & 31;
    const int w    = tid >> 5;
    const int wm = (w & 1) * 64;
    const int wn = (w >> 1) * 32;
    const int g = lane >> 2;
    const int t = lane & 3;

    float acc[4][4][4];
    #pragma unroll
    for (int mt = 0; mt < 4; mt++)
        #pragma unroll
        for (int nt = 0; nt < 4; nt++)
            #pragma unroll
            for (int i = 0; i < 4; i++) acc[mt][nt][i] = 0.f;

    const float* Ald = A + (size_t)(m0 + row) * K + part * 4;
    const float* Wld = W + (size_t)(n0 + row) * K + part * 4;

    float4 av0 = *(const float4*)(Ald);
    float4 av1 = *(const float4*)(Ald + 8);
    float4 wv0 = *(const float4*)(Wld);
    float4 wv1 = *(const float4*)(Wld + 8);

    for (int kt = 0; kt < K; kt += 16){
        const int k0 = part * 4;
        As[k0+0][row] = f2tf32(av0.x); As[k0+1][row] = f2tf32(av0.y);
        As[k0+2][row] = f2tf32(av0.z); As[k0+3][row] = f2tf32(av0.w);
        As[k0+8][row] = f2tf32(av1.x); As[k0+9][row] = f2tf32(av1.y);
        As[k0+10][row] = f2tf32(av1.z); As[k0+11][row] = f2tf32(av1.w);
        Bs[k0+0][row] = f2tf32(wv0.x); Bs[k0+1][row] = f2tf32(wv0.y);
        Bs[k0+2][row] = f2tf32(wv0.z); Bs[k0+3][row] = f2tf32(wv0.w);
        Bs[k0+8][row] = f2tf32(wv1.x); Bs[k0+9][row] = f2tf32(wv1.y);
        Bs[k0+10][row] = f2tf32(wv1.z); Bs[k0+11][row] = f2tf32(wv1.w);
        __syncthreads();
        if (kt + 16 < K){
            av0 = *(const float4*)(Ald + kt + 16);
            av1 = *(const float4*)(Ald + kt + 24);
            wv0 = *(const float4*)(Wld + kt + 16);
            wv1 = *(const float4*)(Wld + kt + 24);
        }
        #pragma unroll
        for (int c = 0; c < 2; c++){
            unsigned af[4][4], bf[4][2];
            #pragma unroll
            for (int mt = 0; mt < 4; mt++){
                const int m = wm + mt*16 + g;
                af[mt][0] = As[c*8 + t][m];
                af[mt][1] = As[c*8 + t][m + 8];
                af[mt][2] = As[c*8 + t + 4][m];
                af[mt][3] = As[c*8 + t + 4][m + 8];
            }
            #pragma unroll
            for (int nt = 0; nt < 4; nt++){
                const int n = wn + nt*8 + g;
                bf[nt][0] = Bs[c*8 + t][n];
                bf[nt][1] = Bs[c*8 + t + 4][n];
            }
            #pragma unroll
            for (int mt = 0; mt < 4; mt++)
                #pragma unroll
                for (int nt = 0; nt < 4; nt++)
                    asm volatile(
                        "mma.sync.aligned.m16n8k8.row.col.f32.tf32.tf32.f32 "
                        "{%0,%1,%2,%3},{%4,%5,%6,%7},{%8,%9},{%0,%1,%2,%3};"
                        : "+f"(acc[mt][nt][0]), "+f"(acc[mt][nt][1]),
                          "+f"(acc[mt][nt][2]), "+f"(acc[mt][nt][3])
                        : "r"(af[mt][0]), "r"(af[mt][1]), "r"(af[mt][2]), "r"(af[mt][3]),
                          "r"(bf[nt][0]), "r"(bf[nt][1]));
        }
        __syncthreads();
    }

    float* out = g_gxT[dir];
    const float* bs = bias + dir * G3;
    #pragma unroll
    for (int mt = 0; mt < 4; mt++){
        #pragma unroll
        for (int nt = 0; nt < 4; nt++){
            const int mr = m0 + wm + mt*16 + g;
            const int nc = n0 + wn + nt*8 + 2*t;
            const float b0 = bs[nc], b1 = bs[nc + 1];
            {
                const int s = mr >> 6, b = mr & 63;
                out[((size_t)s*G3 + nc    )*Bx + b] = acc[mt][nt][0] + b0;
                out[((size_t)s*G3 + nc + 1)*Bx + b] = acc[mt][nt][1] + b1;
            }
            {
                const int m2 = mr + 8;
                const int s = m2 >> 6, b = m2 & 63;
                out[((size_t)s*G3 + nc    )*Bx + b] = acc[mt][nt][2] + b0;
                out[((size_t)s*G3 + nc + 1)*Bx + b] = acc[mt][nt][3] + b1;
            }
        }
    }
}

// =================================================================================
// Cluster GRU layer (R12 structure + vectorized DSMEM push + early gx prefetch +
// split arrive/wait): grid 128 = 32 clusters x 4 CTAs, 384 threads.
// =================================================================================
#define WS_BYTES (96*129*16)                 // 198,144
#define HS_BYTES 4096
#define RED_OFF  (WS_BYTES + 2*HS_BYTES)     // 206,336
#define SMEM_GRU (RED_OFF + 12288)           // 218,624

__global__ void __launch_bounds__(384,1) __cluster_dims__(4,1,1)
gru_layer(
    const float* __restrict__ h0_l,    // [2][B][H]
    const float* __restrict__ whh_l,   // [2][768][256]
    const float* __restrict__ bhh_l,   // [2][768]
    float* __restrict__ hn_out)        // [2][B][H] slice of d_out
{
    extern __shared__ __align__(16) float smem[];
    const unsigned sb = (unsigned)__cvta_generic_to_shared(smem);

    const int cid  = blockIdx.x >> 2;   // cluster id 0..31
    const int q    = (int)ctarank();    // j-quarter 0..3
    const int dir  = cid >> 4;
    const int bgrp = cid & 15;
    const int tid  = threadIdx.x;

    // compute-phase mapping
    const int ks   = tid / 96;          // 0..3 (k-quarter)
    const int rem  = tid - ks*96;
    const int gate = rem >> 5;          // 0..2
    const int jl2  = rem & 31;          // j-pair index

    // epilogue mapping (tid<256)
    const int jl = tid >> 2;            // 0..63
    const int b  = tid & 3;
    const int jglob = q*64 + jl;
    const int bglob = bgrp*4 + b;

    // push mapping (tid<192): 3 remote ranks x 64 16B-chunks of own 1KB region
    const int prk   = (q + 1 + (tid >> 6)) & 3;
    const int pchnk = tid & 63;

    // ---- stage W interleaved: ws[(gate*32+jl2)*129 + k2][4] = {j0e0,j0e1,j1e0,j1e1}
    for (int i = tid; i < 49152; i += 384){
        const int f = i & 3, jsel = f >> 1, e = f & 1;
        const int k2 = (i >> 2) & 127;
        const int rw = i >> 9;                 // 0..95
        const int gg = rw >> 5, jj2 = rw & 31;
        const int jloc = 2*jj2 + jsel;
        smem[((gg*32 + jj2)*129 + k2)*4 + f] =
            whh_l[((size_t)dir*G3 + gg*Hx + q*64 + jloc)*Hx + 2*k2 + e];
    }

    // ---- stage h0 into hsA: [k2][b][e], full 256 j, own 4 batches
    float* hsA = smem + WS_BYTES/4;
    for (int i = tid; i < 1024; i += 384){
        const int j = i >> 2, bb = i & 3;
        hsA[(j >> 1)*8 + bb*2 + (j & 1)] =
            h0_l[(size_t)dir*Bx*Hx + (size_t)(bgrp*4 + bb)*Hx + j];
    }

    // epilogue biases
    float br = 0.f, bz = 0.f, bn = 0.f;
    if (tid < 256){
        br = bhh_l[dir*G3 + jglob];
        bz = bhh_l[dir*G3 + Hx + jglob];
        bn = bhh_l[dir*G3 + 2*Hx + jglob];
    }
    __syncthreads();

    const unsigned wadr = sb + (unsigned)(((gate*32 + jl2)*129 + ks*32)*16);
    float* redp = smem + RED_OFF/4;
    const float* gxb = g_gxT[dir];
    const int hEidx = (jglob >> 1)*8 + b*2 + (jglob & 1);

    int cur = 0;
    for (int t = 0; t < Sx; t++){
        const int ta = dir ? (Sx - 1 - t) : t;
        const unsigned hsC_u = sb + WS_BYTES + (unsigned)cur*HS_BYTES;
        const unsigned hsN_u = sb + WS_BYTES + (unsigned)(cur ^ 1)*HS_BYTES;

        // ---- prefetch gate_x for this step (independent of h); hidden by barrier+compute
        float xr = 0.f, xz = 0.f, xn = 0.f;
        if (tid < 256){
            const float* p = gxb + (size_t)ta*G3*Bx + bglob;
            xr = __ldg(p + (size_t)(0*Hx + jglob)*Bx);
            xz = __ldg(p + (size_t)(1*Hx + jglob)*Bx);
            xn = __ldg(p + (size_t)(2*Hx + jglob)*Bx);
        }

        // ---- wait for previous step's DSMEM pushes (arrive was at end of prev step)
        if (t > 0)
            asm volatile("barrier.cluster.wait.aligned;" ::: "memory");

        float hprev = 0.f;
        if (tid < 256)
            asm volatile("ld.shared.f32 %0,[%1];"
                         : "=f"(hprev) : "r"(hsC_u + (unsigned)(hEidx*4)));

        // ---- compute: 32 k2-iters, 2 j x 4 b x 3-gate-split
        ull aJ0B0=0, aJ0B1=0, aJ0B2=0, aJ0B3=0, aJ1B0=0, aJ1B1=0, aJ1B2=0, aJ1B3=0;
        const unsigned hbase = hsC_u + (unsigned)(ks*32*32);
        #pragma unroll 8
        for (int k = 0; k < 32; k++){
            ull wj0, wj1, hb0, hb1, hb2, hb3;
            asm volatile("ld.shared.v2.u64 {%0,%1},[%2];"
                         : "=l"(wj0), "=l"(wj1) : "r"(wadr + k*16));
            asm volatile("ld.shared.v2.u64 {%0,%1},[%2];"
                         : "=l"(hb0), "=l"(hb1) : "r"(hbase + k*32));
            asm volatile("ld.shared.v2.u64 {%0,%1},[%2];"
                         : "=l"(hb2), "=l"(hb3) : "r"(hbase + k*32 + 16));
            asm("fma.rn.f32x2 %0,%1,%2,%0;" : "+l"(aJ0B0) : "l"(wj0), "l"(hb0));
            asm("fma.rn.f32x2 %0,%1,%2,%0;" : "+l"(aJ0B1) : "l"(wj0), "l"(hb1));
            asm("fma.rn.f32x2 %0,%1,%2,%0;" : "+l"(aJ0B2) : "l"(wj0), "l"(hb2));
            asm("fma.rn.f32x2 %0,%1,%2,%0;" : "+l"(aJ0B3) : "l"(wj0), "l"(hb3));
            asm("fma.rn.f32x2 %0,%1,%2,%0;" : "+l"(aJ1B0) : "l"(wj1), "l"(hb0));
            asm("fma.rn.f32x2 %0,%1,%2,%0;" : "+l"(aJ1B1) : "l"(wj1), "l"(hb1));
            asm("fma.rn.f32x2 %0,%1,%2,%0;" : "+l"(aJ1B2) : "l"(wj1), "l"(hb2));
            asm("fma.rn.f32x2 %0,%1,%2,%0;" : "+l"(aJ1B3) : "l"(wj1), "l"(hb3));
        }
        // collapse k-parity, publish partials: red[(ks*3+gate)*64 + j][b]
        {
            float4 v0, v1; float lo, hi;
            asm("mov.b64 {%0,%1},%2;" : "=f"(lo), "=f"(hi) : "l"(aJ0B0)); v0.x = lo + hi;
            asm("mov.b64 {%0,%1},%2;" : "=f"(lo), "=f"(hi) : "l"(aJ0B1)); v0.y = lo + hi;
            asm("mov.b64 {%0,%1},%2;" : "=f"(lo), "=f"(hi) : "l"(aJ0B2)); v0.z = lo + hi;
            asm("mov.b64 {%0,%1},%2;" : "=f"(lo), "=f"(hi) : "l"(aJ0B3)); v0.w = lo + hi;
            asm("mov.b64 {%0,%1},%2;" : "=f"(lo), "=f"(hi) : "l"(aJ1B0)); v1.x = lo + hi;
            asm("mov.b64 {%0,%1},%2;" : "=f"(lo), "=f"(hi) : "l"(aJ1B1)); v1.y = lo + hi;
            asm("mov.b64 {%0,%1},%2;" : "=f"(lo), "=f"(hi) : "l"(aJ1B2)); v1.z = lo + hi;
            asm("mov.b64 {%0,%1},%2;" : "=f"(lo), "=f"(hi) : "l"(aJ1B3)); v1.w = lo + hi;
            float4* rp = (float4*)(redp + ((ks*3 + gate)*64 + 2*jl2)*4);
            rp[0] = v0;
            rp[1] = v1;
        }
        __syncthreads();

        // ---- epilogue: thread = (jl, b), tid<256; store hnew LOCALLY only
        if (tid < 256){
            float sr = 0.f, sz = 0.f, sn = 0.f;
            #pragma unroll
            for (int kq = 0; kq < 4; kq++){
                sr += redp[((kq*3 + 0)*64 + jl)*4 + b];
                sz += redp[((kq*3 + 1)*64 + jl)*4 + b];
                sn += redp[((kq*3 + 2)*64 + jl)*4 + b];
            }
            const float r = __fdividef(1.f, 1.f + __expf(-(xr + sr + br)));
            const float z = __fdividef(1.f, 1.f + __expf(-(xz + sz + bz)));
            const float targ = xn + r * (sn + bn);
            const float nn = 1.f - __fdividef(2.f, __expf(2.f*targ) + 1.f);
            const float hnew = (1.f - z) * nn + z * hprev;

            asm volatile("st.shared.f32 [%0],%1;"
                         :: "r"(hsN_u + (unsigned)(hEidx*4)), "f"(hnew) : "memory");
            g_io[((size_t)ta*Bx + bglob)*DHx + dir*Hx + jglob] = hnew;
            if (t == Sx - 1)
                hn_out[(size_t)dir*Bx*Hx + (size_t)bglob*Hx + jglob] = hnew;
        }
        __syncthreads();

        // ---- vectorized DSMEM push: own 1KB region -> 3 remote ranks (16B chunks)
        if (t < Sx - 1){
            if (tid < 192){
                const unsigned off = hsN_u + (unsigned)(q*1024 + pchnk*16);
                ull v0, v1;
                asm volatile("ld.shared.v2.u64 {%0,%1},[%2];"
                             : "=l"(v0), "=l"(v1) : "r"(off));
                asm volatile(
                    "{ .reg .b32 ra;\n\t"
                    "mapa.shared::cluster.u32 ra, %0, %1;\n\t"
                    "st.shared::cluster.v2.b64 [ra], {%2,%3}; }"
                    :: "r"(off), "r"(prk), "l"(v0), "l"(v1) : "memory");
            }
            asm volatile("barrier.cluster.arrive.aligned;" ::: "memory");
        }
        cur ^= 1;
    }
}

// =================================================================================
extern "C" void kernel_launch(void* const* d_in, const int* in_sizes, int n_in,
                              void* d_out, int out_size)
{
    const float* x     = (const float*)d_in[0];   // (512,64,128)
    const float* h0    = (const float*)d_in[1];   // (12,64,256)
    const float* w_ih0 = (const float*)d_in[2];   // (2,768,128)
    const float* w_ih  = (const float*)d_in[3];   // (5,2,768,512)
    const float* w_hh  = (const float*)d_in[4];   // (6,2,768,256)
    const float* b_ih  = (const float*)d_in[5];   // (6,2,768)
    const float* b_hh  = (const float*)d_in[6];   // (6,2,768)
    float* out = (float*)d_out;                   // (12,64,256)

    cudaFuncSetAttribute(gru_layer, cudaFuncAttributeMaxDynamicSharedMemorySize, SMEM_GRU);

    for (int layer = 0; layer < Lx; layer++){
        dim3 gg(G3/128, M_TOT/128, 2);
        if (layer == 0){
            gatex_gemm<128><<<gg, 256>>>(x, w_ih0, b_ih);
        } else {
            gatex_gemm<512><<<gg, 256>>>(
                x,
                w_ih + (size_t)(layer-1) * 2 * G3 * 512,
                b_ih + (size_t)layer * 2 * G3);
        }
        gru_layer<<<128, 384, SMEM_GRU>>>(
            h0   + (size_t)layer * 2 * Bx * Hx,
            w_hh + (size_t)layer * 2 * G3 * Hx,
            b_hh + (size_t)layer * 2 * G3,
            out  + (size_t)layer * 2 * Bx * Hx);
    }
}